// round 11
// baseline (speedup 1.0000x reference)
#include <cuda_runtime.h>
#include <cuda_bf16.h>
#include <cstdint>
#include <cstddef>

#define BnW   2048
#define NW    144
#define DIM   256
#define NH    8
#define HD    32
#define NTOK  (BnW * NW)            /* 294912 */
#define QKVN  (3 * DIM)             /* 768 */
#define KSTORE 512                  /* split-bf16 stored K: [hi|lo] */
#define SCALE 0.17677669529663687f

// ---------------- scratch (device globals: allocation-free rule) -------------
__device__ uint32_t      g_qkv[(size_t)NTOK * QKVN];     // packed (hi|lo) bf16 q|k|v
__device__ __nv_bfloat16 g_ax[(size_t)NTOK * KSTORE];    // x ext [Ah|Al]
__device__ __nv_bfloat16 g_attx[(size_t)NTOK * KSTORE];  // attn out ext [Oh|Ol]
__device__ __nv_bfloat16 g_bq[(size_t)QKVN * KSTORE];    // qkv_w ext [Bh|Bl] (q-cols scaled)
__device__ __nv_bfloat16 g_bp[(size_t)DIM * KSTORE];     // proj_w ext
__device__ float         g_sbias[QKVN];                  // scaled qkv bias
__device__ float         g_bias[NH * NW * NW];           // [h][n][m] RPB

// ======================= baseline-PTX tensor-core helpers ====================
__device__ __forceinline__ uint32_t smem_u32(const void* p) {
    uint32_t a;
    asm("{ .reg .u64 t; cvta.to.shared.u64 t, %1; cvt.u32.u64 %0, t; }"
        : "=r"(a) : "l"(p));
    return a;
}
#define LDMX4(r0, r1, r2, r3, addr) \
    asm volatile("ldmatrix.sync.aligned.m8n8.x4.shared.b16 {%0,%1,%2,%3}, [%4];" \
                 : "=r"(r0), "=r"(r1), "=r"(r2), "=r"(r3) : "r"(addr))
#define LDMX4T(r0, r1, r2, r3, addr) \
    asm volatile("ldmatrix.sync.aligned.m8n8.x4.trans.shared.b16 {%0,%1,%2,%3}, [%4];" \
                 : "=r"(r0), "=r"(r1), "=r"(r2), "=r"(r3) : "r"(addr))
#define MMA16816(d, a, b0, b1) \
    asm volatile("mma.sync.aligned.m16n8k16.row.col.f32.bf16.bf16.f32 " \
                 "{%0,%1,%2,%3}, {%4,%5,%6,%7}, {%8,%9}, {%0,%1,%2,%3};" \
                 : "+f"((d)[0]), "+f"((d)[1]), "+f"((d)[2]), "+f"((d)[3]) \
                 : "r"((a)[0]), "r"((a)[1]), "r"((a)[2]), "r"((a)[3]), \
                   "r"(b0), "r"(b1))
#define CPASYNC16(s, g) \
    asm volatile("cp.async.cg.shared.global [%0], [%1], 16;" :: "r"(s), "l"(g))
#define CP_COMMIT() asm volatile("cp.async.commit_group;" ::: "memory")
#define CP_WAIT1()  asm volatile("cp.async.wait_group 1;" ::: "memory")
#define CP_WAIT0()  asm volatile("cp.async.wait_group 0;" ::: "memory")

// ======================= split-bf16 helpers ==================================
__device__ __forceinline__ void bf_split(float f, unsigned short& h, unsigned short& l) {
    __nv_bfloat16 hb = __float2bfloat16(f);
    __nv_bfloat16 lb = __float2bfloat16(f - __bfloat162float(hb));
    h = __bfloat16_as_ushort(hb);
    l = __bfloat16_as_ushort(lb);
}
__device__ __forceinline__ uint32_t pack_hl(float f) {
    unsigned short h, l;
    bf_split(f, h, l);
    return (uint32_t)h | ((uint32_t)l << 16);
}
__device__ __forceinline__ void split2(float x, float y, uint32_t& hp, uint32_t& lp) {
    unsigned short hx, lx, hy, ly;
    bf_split(x, hx, lx);
    bf_split(y, hy, ly);
    hp = (uint32_t)hx | ((uint32_t)hy << 16);
    lp = (uint32_t)lx | ((uint32_t)ly << 16);
}

// x [NTOK,256] fp32 -> g_ax [NTOK,512] = [Ah|Al]
__global__ __launch_bounds__(256) void conv_x_kernel(const float* __restrict__ x) {
    size_t i = (size_t)blockIdx.x * 256 + threadIdx.x;   // over NTOK*64
    size_t row = i >> 6;
    int c4 = (int)(i & 63) * 4;
    float4 v = *reinterpret_cast<const float4*>(x + row * DIM + c4);
    ushort4 hv, lv;
    bf_split(v.x, hv.x, lv.x); bf_split(v.y, hv.y, lv.y);
    bf_split(v.z, hv.z, lv.z); bf_split(v.w, hv.w, lv.w);
    __nv_bfloat16* base = g_ax + row * KSTORE;
    *reinterpret_cast<ushort4*>(base + c4)       = hv;
    *reinterpret_cast<ushort4*>(base + 256 + c4) = lv;
}

// weight conversions (grid = 1024 blocks)
__global__ __launch_bounds__(256) void conv_w_kernel(
    const float* __restrict__ qkv_w, const float* __restrict__ proj_w) {
    int blk = blockIdx.x;
    const float* w;
    __nv_bfloat16* Bext;
    int N, nscale, i;
    if (blk < 768) {
        w = qkv_w; Bext = g_bq; N = QKVN; nscale = DIM;
        i = blk * 256 + threadIdx.x;
    } else {
        w = proj_w; Bext = g_bp; N = DIM; nscale = 0;
        i = (blk - 768) * 256 + threadIdx.x;
    }
    int n = i >> 8, k = i & 255;
    float val = w[k * N + n];
    if (n < nscale) val *= SCALE;
    unsigned short h, l;
    bf_split(val, h, l);
    Bext[(size_t)n * KSTORE + k]       = __ushort_as_bfloat16(h);
    Bext[(size_t)n * KSTORE + 256 + k] = __ushort_as_bfloat16(l);
}

// rpb gather + scaled qkv bias (grid = 84)
__global__ __launch_bounds__(256) void bias_all_kernel(
    const float* __restrict__ rpb, const int* __restrict__ rel,
    const float* __restrict__ qkv_b) {
    int blk = blockIdx.x;
    if (blk < 81) {
        int idx = blk * 256 + threadIdx.x;
        if (idx < NW * NW) {
            int r = rel[idx];
#pragma unroll
            for (int h = 0; h < NH; h++)
                g_bias[h * (NW * NW) + idx] = rpb[r * NH + h];
        }
    } else {
        int i = (blk - 81) * 256 + threadIdx.x;
        if (i < QKVN) g_sbias[i] = qkv_b[i] * (i < DIM ? SCALE : 1.0f);
    }
}

// ======================= mma.sync GEMM v2: tile 128(M) x 64(N) ===============
// 3 CTAs/SM: smem 61440/CTA, acc 32 regs/thread. Grouped K as before.
#define SPITCH 80
#define AH_OFF 0
#define AL_OFF 10240
#define BH_OFF 20480
#define BL_OFF 25600
#define STAGE_STRIDE 30720
#define SMEM_GEMM (2 * STAGE_STRIDE)        /* 61440 */

template <bool PACK>
__global__ __launch_bounds__(256, 3) void gemm_mma_kernel(
    const __nv_bfloat16* __restrict__ Aext,
    const __nv_bfloat16* __restrict__ Bext,
    const float* __restrict__ bias,
    void* __restrict__ Cout, int Ntot) {
    extern __shared__ char gsm[];
    const uint32_t sb = smem_u32(gsm);

    const int tid = threadIdx.x;
    const int w = tid >> 5, l = tid & 31;
    const int wm = w >> 1, wn = w & 1;          // 4M x 2N warp grid
    const int tileN = blockIdx.x, tileM = blockIdx.y;

    const char* Ab = reinterpret_cast<const char*>(Aext) +
                     (size_t)tileM * 128 * (KSTORE * 2);
    const char* Bb = reinterpret_cast<const char*>(Bext) +
                     (size_t)tileN * 64 * (KSTORE * 2);

    const int arow = tid >> 1;                  // 0..127
    const int aseg = (tid & 1) * 32;            // 0 or 32
    const int brow = tid >> 2;                  // 0..63
    const int bseg = (tid & 3) * 16;            // 0..48

    float acc[2][4][4];
#pragma unroll
    for (int mf = 0; mf < 2; mf++)
#pragma unroll
        for (int nf = 0; nf < 4; nf++)
#pragma unroll
            for (int r = 0; r < 4; r++) acc[mf][nf][r] = 0.f;

#define ISSUE_GROUP(gg) do {                                                      \
        const int _g = (gg);                                                      \
        const uint32_t _st = sb + (uint32_t)(_g & 1) * STAGE_STRIDE;              \
        const size_t _ga = (size_t)arow * (KSTORE * 2) + _g * 64;                 \
        const size_t _gb = (size_t)brow * (KSTORE * 2) + _g * 64;                 \
        CPASYNC16(_st + AH_OFF + arow * SPITCH + aseg,      Ab + _ga + aseg);     \
        CPASYNC16(_st + AH_OFF + arow * SPITCH + aseg + 16, Ab + _ga + aseg + 16);\
        CPASYNC16(_st + AL_OFF + arow * SPITCH + aseg,      Ab + _ga + 512 + aseg);\
        CPASYNC16(_st + AL_OFF + arow * SPITCH + aseg + 16, Ab + _ga + 512 + aseg + 16);\
        CPASYNC16(_st + BH_OFF + brow * SPITCH + bseg,      Bb + _gb + bseg);     \
        CPASYNC16(_st + BL_OFF + brow * SPITCH + bseg,      Bb + _gb + 512 + bseg);\
        CP_COMMIT();                                                              \
    } while (0)

    ISSUE_GROUP(0);
    ISSUE_GROUP(1);

    const uint32_t aRowOff = (uint32_t)(wm * 32 + (l & 15)) * SPITCH + (l >> 4) * 16;
    const uint32_t bRowOff = (uint32_t)(wn * 32 + (l >> 4) * 8 + (l & 7)) * SPITCH +
                             ((l >> 3) & 1) * 16;

    for (int g = 0; g < 8; g++) {
        if (g < 7) CP_WAIT1(); else CP_WAIT0();
        __syncthreads();

        const uint32_t st = sb + (uint32_t)(g & 1) * STAGE_STRIDE;
        const uint32_t aH = st + AH_OFF + aRowOff;
        const uint32_t aL = st + AL_OFF + aRowOff;
        const uint32_t bH = st + BH_OFF + bRowOff;
        const uint32_t bL = st + BL_OFF + bRowOff;

#pragma unroll
        for (int ks = 0; ks < 2; ks++) {
            uint32_t ah[2][4], al[2][4], bf[2][4];
#pragma unroll
            for (int mf = 0; mf < 2; mf++)
                LDMX4(ah[mf][0], ah[mf][1], ah[mf][2], ah[mf][3],
                      aH + mf * (16 * SPITCH) + ks * 32);
#pragma unroll
            for (int n2 = 0; n2 < 2; n2++)
                LDMX4(bf[n2][0], bf[n2][1], bf[n2][2], bf[n2][3],
                      bH + n2 * (16 * SPITCH) + ks * 32);
#pragma unroll
            for (int mf = 0; mf < 2; mf++)
#pragma unroll
                for (int nf = 0; nf < 4; nf++)
                    MMA16816(acc[mf][nf], ah[mf],
                             bf[nf >> 1][(nf & 1) * 2],
                             bf[nf >> 1][(nf & 1) * 2 + 1]);
#pragma unroll
            for (int mf = 0; mf < 2; mf++)
                LDMX4(al[mf][0], al[mf][1], al[mf][2], al[mf][3],
                      aL + mf * (16 * SPITCH) + ks * 32);
#pragma unroll
            for (int mf = 0; mf < 2; mf++)
#pragma unroll
                for (int nf = 0; nf < 4; nf++)
                    MMA16816(acc[mf][nf], al[mf],
                             bf[nf >> 1][(nf & 1) * 2],
                             bf[nf >> 1][(nf & 1) * 2 + 1]);
#pragma unroll
            for (int n2 = 0; n2 < 2; n2++)
                LDMX4(bf[n2][0], bf[n2][1], bf[n2][2], bf[n2][3],
                      bL + n2 * (16 * SPITCH) + ks * 32);
#pragma unroll
            for (int mf = 0; mf < 2; mf++)
#pragma unroll
                for (int nf = 0; nf < 4; nf++)
                    MMA16816(acc[mf][nf], ah[mf],
                             bf[nf >> 1][(nf & 1) * 2],
                             bf[nf >> 1][(nf & 1) * 2 + 1]);
        }
        __syncthreads();
        if (g + 2 < 8) ISSUE_GROUP(g + 2);
    }
#undef ISSUE_GROUP

    const int rbase = tileM * 128 + wm * 32 + (l >> 2);
    const int cbase = tileN * 64 + wn * 32 + (l & 3) * 2;
#pragma unroll
    for (int mf = 0; mf < 2; mf++) {
#pragma unroll
        for (int nf = 0; nf < 4; nf++) {
            const int col = cbase + nf * 8;
            const float b0 = bias[col], b1 = bias[col + 1];
            const size_t r0 = (size_t)(rbase + mf * 16) * Ntot + col;
            const size_t r1 = r0 + (size_t)8 * Ntot;
            if (PACK) {
                uint32_t* C = reinterpret_cast<uint32_t*>(Cout);
                *reinterpret_cast<uint2*>(C + r0) =
                    make_uint2(pack_hl(acc[mf][nf][0] + b0), pack_hl(acc[mf][nf][1] + b1));
                *reinterpret_cast<uint2*>(C + r1) =
                    make_uint2(pack_hl(acc[mf][nf][2] + b0), pack_hl(acc[mf][nf][3] + b1));
            } else {
                float* C = reinterpret_cast<float*>(Cout);
                *reinterpret_cast<float2*>(C + r0) =
                    make_float2(acc[mf][nf][0] + b0, acc[mf][nf][1] + b1);
                *reinterpret_cast<float2*>(C + r1) =
                    make_float2(acc[mf][nf][2] + b0, acc[mf][nf][3] + b1);
            }
        }
    }
}

// ======================= tensor-core attention v5.1 ==========================
#define QPITCH 144
#define KPITCH 144
#define VPITCH 144
#define OFF_Q   0
#define OFF_K   (144 * QPITCH)            /* 20736 */
#define OFF_V   (OFF_K + 144 * KPITCH)    /* 41472 */
#define SMEM_ATTN (OFF_V + 144 * VPITCH)  /* 62208 */

__global__ __launch_bounds__(288, 2) void attn_tc_kernel() {
    extern __shared__ char sm[];
    const uint32_t sb = smem_u32(sm);
    const int tid = threadIdx.x, l = tid & 31, w = tid >> 5;
    const int h = blockIdx.x, b = blockIdx.y;
    const size_t tokBase = (size_t)b * NW;

    // ---- stage Q, K, V (row-major hi|lo, wide 8B stores) ----
    for (int idx = tid; idx < 144 * 8; idx += 288) {
        int r = idx >> 3, d4 = (idx & 7) * 4;
        const uint32_t* src = g_qkv + (tokBase + r) * QKVN + h * HD + d4;
        char* dst = sm + r * QPITCH + d4 * 2;   // OFF_Q = 0
#pragma unroll
        for (int mtx = 0; mtx < 3; mtx++) {     // Q, K, V
            uint4 e = *reinterpret_cast<const uint4*>(src + mtx * DIM);
            char* p = dst + mtx * (144 * QPITCH);
            *reinterpret_cast<uint2*>(p) =
                make_uint2(__byte_perm(e.x, e.y, 0x5410), __byte_perm(e.z, e.w, 0x5410));
            *reinterpret_cast<uint2*>(p + 64) =
                make_uint2(__byte_perm(e.x, e.y, 0x7632), __byte_perm(e.z, e.w, 0x7632));
        }
    }
    __syncthreads();    // the only block barrier

    // ---- QK^T: S[16 x 144] per warp; grouped fragment reuse ----
    float accS[18][4];
#pragma unroll
    for (int j = 0; j < 18; j++)
#pragma unroll
        for (int e = 0; e < 4; e++) accS[j][e] = 0.f;

    const uint32_t aBase = sb + OFF_Q + (w * 16 + (l & 15)) * QPITCH + (l >> 4) * 16;
    const uint32_t bBase = sb + OFF_K +
        (((l >> 4) & 1) * 8 + (l & 7)) * KPITCH + ((l >> 3) & 1) * 16;
#pragma unroll
    for (int ks = 0; ks < 2; ks++) {
        uint32_t ah[4], al[4];
        LDMX4(ah[0], ah[1], ah[2], ah[3], aBase + ks * 32);        // Qh
        LDMX4(al[0], al[1], al[2], al[3], aBase + 64 + ks * 32);   // Ql
#pragma unroll
        for (int jp = 0; jp < 9; jp++) {
            uint32_t bf[4];
            LDMX4(bf[0], bf[1], bf[2], bf[3],
                  bBase + jp * (16 * KPITCH) + ks * 32);           // Kh
            MMA16816(accS[jp * 2],     ah, bf[0], bf[1]);
            MMA16816(accS[jp * 2 + 1], ah, bf[2], bf[3]);
            MMA16816(accS[jp * 2],     al, bf[0], bf[1]);
            MMA16816(accS[jp * 2 + 1], al, bf[2], bf[3]);
            LDMX4(bf[0], bf[1], bf[2], bf[3],
                  bBase + jp * (16 * KPITCH) + 64 + ks * 32);      // Kl
            MMA16816(accS[jp * 2],     ah, bf[0], bf[1]);
            MMA16816(accS[jp * 2 + 1], ah, bf[2], bf[3]);
        }
    }

    // ---- bias add + row max ----
    const float* bh = g_bias + h * (NW * NW);
    const int r0 = w * 16 + (l >> 2);
    float rmax0 = -1e30f, rmax1 = -1e30f;
#pragma unroll
    for (int j = 0; j < 18; j++) {
        const int c = j * 8 + (l & 3) * 2;
        float2 b0 = *reinterpret_cast<const float2*>(bh + r0 * NW + c);
        float2 b1 = *reinterpret_cast<const float2*>(bh + (r0 + 8) * NW + c);
        accS[j][0] += b0.x; accS[j][1] += b0.y;
        accS[j][2] += b1.x; accS[j][3] += b1.y;
        rmax0 = fmaxf(rmax0, fmaxf(accS[j][0], accS[j][1]));
        rmax1 = fmaxf(rmax1, fmaxf(accS[j][2], accS[j][3]));
    }
#pragma unroll
    for (int o = 1; o <= 2; o <<= 1) {
        rmax0 = fmaxf(rmax0, __shfl_xor_sync(0xffffffff, rmax0, o));
        rmax1 = fmaxf(rmax1, __shfl_xor_sync(0xffffffff, rmax1, o));
    }

    // ---- exp + row sum ----
    float rsum0 = 0.f, rsum1 = 0.f;
#pragma unroll
    for (int j = 0; j < 18; j++) {
        accS[j][0] = __expf(accS[j][0] - rmax0);
        accS[j][1] = __expf(accS[j][1] - rmax0);
        accS[j][2] = __expf(accS[j][2] - rmax1);
        accS[j][3] = __expf(accS[j][3] - rmax1);
        rsum0 += accS[j][0] + accS[j][1];
        rsum1 += accS[j][2] + accS[j][3];
    }
#pragma unroll
    for (int o = 1; o <= 2; o <<= 1) {
        rsum0 += __shfl_xor_sync(0xffffffff, rsum0, o);
        rsum1 += __shfl_xor_sync(0xffffffff, rsum1, o);
    }
    const float inv0 = 1.0f / rsum0;
    const float inv1 = 1.0f / rsum1;

    // ---- PV: inline P conversion; V via ldmatrix.trans ----
    float accO[4][4];
#pragma unroll
    for (int j = 0; j < 4; j++)
#pragma unroll
        for (int e = 0; e < 4; e++) accO[j][e] = 0.f;

    const uint32_t vLane = sb + OFF_V + (l & 15) * VPITCH + (l >> 4) * 16;
#pragma unroll
    for (int kk = 0; kk < 9; kk++) {
        uint32_t ph[4], pl[4];
        {
            const int j0 = 2 * kk, j1 = 2 * kk + 1;
            split2(accS[j0][0] * inv0, accS[j0][1] * inv0, ph[0], pl[0]);
            split2(accS[j0][2] * inv1, accS[j0][3] * inv1, ph[1], pl[1]);
            split2(accS[j1][0] * inv0, accS[j1][1] * inv0, ph[2], pl[2]);
            split2(accS[j1][2] * inv1, accS[j1][3] * inv1, ph[3], pl[3]);
        }
        const uint32_t vk = vLane + kk * (16 * VPITCH);
#pragma unroll
        for (int jp = 0; jp < 2; jp++) {
            uint32_t vf[4];
            LDMX4T(vf[0], vf[1], vf[2], vf[3], vk + jp * 32);        // Vh
            MMA16816(accO[2 * jp],     ph, vf[0], vf[1]);
            MMA16816(accO[2 * jp + 1], ph, vf[2], vf[3]);
            MMA16816(accO[2 * jp],     pl, vf[0], vf[1]);
            MMA16816(accO[2 * jp + 1], pl, vf[2], vf[3]);
            LDMX4T(vf[0], vf[1], vf[2], vf[3], vk + jp * 32 + 64);   // Vl
            MMA16816(accO[2 * jp],     ph, vf[0], vf[1]);
            MMA16816(accO[2 * jp + 1], ph, vf[2], vf[3]);
        }
    }

    // ---- write O ext [Oh|Ol] directly ----
#pragma unroll
    for (int j = 0; j < 4; j++) {
        const int cc = j * 8 + (l & 3) * 2;
        uint32_t hp0, lp0, hp1, lp1;
        split2(accO[j][0], accO[j][1], hp0, lp0);
        split2(accO[j][2], accO[j][3], hp1, lp1);
        __nv_bfloat16* o0 = g_attx + (tokBase + r0) * KSTORE + h * HD + cc;
        __nv_bfloat16* o1 = g_attx + (tokBase + r0 + 8) * KSTORE + h * HD + cc;
        *reinterpret_cast<uint32_t*>(o0)       = hp0;
        *reinterpret_cast<uint32_t*>(o0 + 256) = lp0;
        *reinterpret_cast<uint32_t*>(o1)       = hp1;
        *reinterpret_cast<uint32_t*>(o1 + 256) = lp1;
    }
}

// ---------------- launch ------------------------------------------------------
extern "C" void kernel_launch(void* const* d_in, const int* in_sizes, int n_in,
                              void* d_out, int out_size) {
    const float* x      = (const float*)d_in[0];
    const float* qkv_w  = (const float*)d_in[1];
    const float* qkv_b  = (const float*)d_in[2];
    const float* proj_w = (const float*)d_in[3];
    const float* proj_b = (const float*)d_in[4];
    const float* rpb    = (const float*)d_in[5];
    const int*   rel    = (const int*)d_in[6];

    uint32_t* qkvbuf = nullptr;
    __nv_bfloat16 *axp = nullptr, *attxp = nullptr, *bqp = nullptr, *bpp = nullptr;
    float* sbp = nullptr;
    cudaGetSymbolAddress((void**)&qkvbuf, g_qkv);
    cudaGetSymbolAddress((void**)&axp,   g_ax);
    cudaGetSymbolAddress((void**)&attxp, g_attx);
    cudaGetSymbolAddress((void**)&bqp,   g_bq);
    cudaGetSymbolAddress((void**)&bpp,   g_bp);
    cudaGetSymbolAddress((void**)&sbp,   g_sbias);

    static bool attr_done = false;
    if (!attr_done) {
        cudaFuncSetAttribute(attn_tc_kernel,
                             cudaFuncAttributeMaxDynamicSharedMemorySize, SMEM_ATTN);
        cudaFuncSetAttribute(gemm_mma_kernel<true>,
                             cudaFuncAttributeMaxDynamicSharedMemorySize, SMEM_GEMM);
        cudaFuncSetAttribute(gemm_mma_kernel<false>,
                             cudaFuncAttributeMaxDynamicSharedMemorySize, SMEM_GEMM);
        attr_done = true;
    }

    // order: profiled launch slot (index 3) = QKV GEMM (new version)
    conv_x_kernel<<<(NTOK * 64) / 256, 256>>>(x);                    // 0
    conv_w_kernel<<<1024, 256>>>(qkv_w, proj_w);                     // 1
    bias_all_kernel<<<84, 256>>>(rpb, rel, qkv_b);                   // 2
    gemm_mma_kernel<true><<<dim3(QKVN / 64, NTOK / 128), 256, SMEM_GEMM>>>(
        axp, bqp, sbp, qkvbuf, QKVN);                                // 3 <- profiled
    attn_tc_kernel<<<dim3(NH, BnW), 288, SMEM_ATTN>>>();             // 4
    gemm_mma_kernel<false><<<dim3(DIM / 64, NTOK / 128), 256, SMEM_GEMM>>>(
        attxp, bpp, proj_b, d_out, DIM);                             // 5
}

// round 13
// speedup vs baseline: 1.1198x; 1.1198x over previous
#include <cuda_runtime.h>
#include <cuda_bf16.h>
#include <cstdint>
#include <cstddef>

#define BnW   2048
#define NW    144
#define DIM   256
#define NH    8
#define HD    32
#define NTOK  (BnW * NW)            /* 294912 */
#define QKVN  (3 * DIM)             /* 768 */
#define KSTORE 512                  /* split-bf16 stored K: [hi|lo] */
#define SCALE 0.17677669529663687f

// ---------------- scratch (device globals: allocation-free rule) -------------
__device__ uint32_t      g_qkv[(size_t)NTOK * QKVN];     // packed (hi|lo) bf16 q|k|v
__device__ __nv_bfloat16 g_attx[(size_t)NTOK * KSTORE];  // attn out ext [Oh|Ol]
__device__ __nv_bfloat16 g_bq[(size_t)QKVN * KSTORE];    // qkv_w ext [Bh|Bl] (q-cols scaled)
__device__ __nv_bfloat16 g_bp[(size_t)DIM * KSTORE];     // proj_w ext
__device__ float         g_sbias[QKVN];                  // scaled qkv bias
__device__ float         g_bias[NH * NW * NW];           // [h][n][m] RPB

// ======================= baseline-PTX tensor-core helpers ====================
__device__ __forceinline__ uint32_t smem_u32(const void* p) {
    uint32_t a;
    asm("{ .reg .u64 t; cvta.to.shared.u64 t, %1; cvt.u32.u64 %0, t; }"
        : "=r"(a) : "l"(p));
    return a;
}
#define LDMX4(r0, r1, r2, r3, addr) \
    asm volatile("ldmatrix.sync.aligned.m8n8.x4.shared.b16 {%0,%1,%2,%3}, [%4];" \
                 : "=r"(r0), "=r"(r1), "=r"(r2), "=r"(r3) : "r"(addr))
#define LDMX4T(r0, r1, r2, r3, addr) \
    asm volatile("ldmatrix.sync.aligned.m8n8.x4.trans.shared.b16 {%0,%1,%2,%3}, [%4];" \
                 : "=r"(r0), "=r"(r1), "=r"(r2), "=r"(r3) : "r"(addr))
#define MMA16816(d, a, b0, b1) \
    asm volatile("mma.sync.aligned.m16n8k16.row.col.f32.bf16.bf16.f32 " \
                 "{%0,%1,%2,%3}, {%4,%5,%6,%7}, {%8,%9}, {%0,%1,%2,%3};" \
                 : "+f"((d)[0]), "+f"((d)[1]), "+f"((d)[2]), "+f"((d)[3]) \
                 : "r"((a)[0]), "r"((a)[1]), "r"((a)[2]), "r"((a)[3]), \
                   "r"(b0), "r"(b1))
#define CPASYNC16(s, g) \
    asm volatile("cp.async.cg.shared.global [%0], [%1], 16;" :: "r"(s), "l"(g))
#define CP_COMMIT() asm volatile("cp.async.commit_group;" ::: "memory")
#define CP_WAIT1()  asm volatile("cp.async.wait_group 1;" ::: "memory")
#define CP_WAIT0()  asm volatile("cp.async.wait_group 0;" ::: "memory")

// ======================= split-bf16 helpers ==================================
__device__ __forceinline__ void bf_split(float f, unsigned short& h, unsigned short& l) {
    __nv_bfloat16 hb = __float2bfloat16(f);
    __nv_bfloat16 lb = __float2bfloat16(f - __bfloat162float(hb));
    h = __bfloat16_as_ushort(hb);
    l = __bfloat16_as_ushort(lb);
}
__device__ __forceinline__ uint32_t pack_hl(float f) {
    unsigned short h, l;
    bf_split(f, h, l);
    return (uint32_t)h | ((uint32_t)l << 16);
}
__device__ __forceinline__ void split2(float x, float y, uint32_t& hp, uint32_t& lp) {
    unsigned short hx, lx, hy, ly;
    bf_split(x, hx, lx);
    bf_split(y, hy, ly);
    hp = (uint32_t)hx | ((uint32_t)hy << 16);
    lp = (uint32_t)lx | ((uint32_t)ly << 16);
}

// weight conversions (grid = 1024 blocks)
__global__ __launch_bounds__(256) void conv_w_kernel(
    const float* __restrict__ qkv_w, const float* __restrict__ proj_w) {
    int blk = blockIdx.x;
    const float* w;
    __nv_bfloat16* Bext;
    int N, nscale, i;
    if (blk < 768) {
        w = qkv_w; Bext = g_bq; N = QKVN; nscale = DIM;
        i = blk * 256 + threadIdx.x;
    } else {
        w = proj_w; Bext = g_bp; N = DIM; nscale = 0;
        i = (blk - 768) * 256 + threadIdx.x;
    }
    int n = i >> 8, k = i & 255;
    float val = w[k * N + n];
    if (n < nscale) val *= SCALE;
    unsigned short h, l;
    bf_split(val, h, l);
    Bext[(size_t)n * KSTORE + k]       = __ushort_as_bfloat16(h);
    Bext[(size_t)n * KSTORE + 256 + k] = __ushort_as_bfloat16(l);
}

// rpb gather
__global__ __launch_bounds__(256) void build_bias_kernel(
    const float* __restrict__ rpb, const int* __restrict__ rel) {
    int idx = blockIdx.x * 256 + threadIdx.x;
    if (idx < NW * NW) {
        int r = rel[idx];
#pragma unroll
        for (int h = 0; h < NH; h++)
            g_bias[h * (NW * NW) + idx] = rpb[r * NH + h];
    }
}
// scaled qkv bias
__global__ void prep_bias_kernel(const float* __restrict__ qkv_b) {
    int i = blockIdx.x * 256 + threadIdx.x;
    if (i < QKVN) g_sbias[i] = qkv_b[i] * (i < DIM ? SCALE : 1.0f);
}

#define SPITCH 80

// ======================= fused QKV GEMM ======================================
// C[tok, 768] = split2(x) @ g_bq^T + sbias, output packed (hi|lo).
// A staged from fp32 x via LDG+bf_split+STS (conv_x fused away).
// One __syncthreads per K-group; A double-buffered, B cp.async 3-ring.
#define QA_STAGE 20480                       /* Ah 10240 + Al 10240 */
#define QB_STAGE 20480                       /* Bh 10240 + Bl 10240 */
#define QSM_B   (2 * QA_STAGE)               /* 40960 */
#define SMEM_QKV (QSM_B + 3 * QB_STAGE)      /* 102400 */

__global__ __launch_bounds__(256, 2) void gemm_qkv_kernel(
    const float* __restrict__ X,
    const __nv_bfloat16* __restrict__ Bext,
    const float* __restrict__ bias,
    uint32_t* __restrict__ Cout) {
    extern __shared__ char gsm[];
    const uint32_t sb = smem_u32(gsm);

    const int tid = threadIdx.x;
    const int w = tid >> 5, l = tid & 31;
    const int wm = w & 1, wn = w >> 1;
    const int tileN = blockIdx.x, tileM = blockIdx.y;

    const float* Xb = X + (size_t)tileM * 128 * DIM;
    const char* Bb = reinterpret_cast<const char*>(Bext) +
                     (size_t)tileN * 128 * (KSTORE * 2);

    const int arow = tid >> 1;               // 0..127
    const int aseg = (tid & 1) * 32;         // byte offset in 64B hi-chunk
    const int lrow = tid >> 2;               // 0..63
    const int lseg = (tid & 3) * 16;

    float acc[4][4][4];
#pragma unroll
    for (int mf = 0; mf < 4; mf++)
#pragma unroll
        for (int nf = 0; nf < 4; nf++)
#pragma unroll
            for (int r = 0; r < 4; r++) acc[mf][nf][r] = 0.f;

#define ISSUE_B(gg) do {                                                          \
        const int _g = (gg);                                                      \
        const uint32_t _sB = sb + QSM_B + (uint32_t)(_g % 3) * QB_STAGE;          \
        const size_t _r1 = (size_t)lrow * (KSTORE * 2);                           \
        const size_t _r2 = (size_t)(lrow + 64) * (KSTORE * 2);                    \
        const int _hc = _g * 64 + lseg;                                           \
        const int _lc = 512 + _g * 64 + lseg;                                     \
        CPASYNC16(_sB + lrow * SPITCH + lseg,              Bb + _r1 + _hc);       \
        CPASYNC16(_sB + (lrow + 64) * SPITCH + lseg,       Bb + _r2 + _hc);       \
        CPASYNC16(_sB + 10240 + lrow * SPITCH + lseg,        Bb + _r1 + _lc);     \
        CPASYNC16(_sB + 10240 + (lrow + 64) * SPITCH + lseg, Bb + _r2 + _lc);     \
        CP_COMMIT();                                                              \
    } while (0)

    ISSUE_B(0);
    ISSUE_B(1);

    // A group g covers fp32 x cols [g*32, g*32+32); this thread owns 16 of them
    const float* fbase = Xb + (size_t)arow * DIM + (aseg >> 1);
    float4 av0, av1, av2, av3;
    av0 = *reinterpret_cast<const float4*>(fbase + 0);
    av1 = *reinterpret_cast<const float4*>(fbase + 4);
    av2 = *reinterpret_cast<const float4*>(fbase + 8);
    av3 = *reinterpret_cast<const float4*>(fbase + 12);

    const uint32_t aRowOff = (uint32_t)(wm * 64 + (l & 15)) * SPITCH + (l >> 4) * 16;
    const uint32_t bRowOff = (uint32_t)(wn * 32 + ((l >> 4) * 8 + (l & 7))) * SPITCH +
                             ((l >> 3) & 1) * 16;

    for (int g = 0; g < 8; g++) {
        if (g < 7) CP_WAIT1(); else CP_WAIT0();

        // STS A(g): split fp32 -> (hi, lo) bf16 rows
        {
            char* ast = gsm + (g & 1) * QA_STAGE + arow * SPITCH + aseg;
            uint4 hi0, hi1, lo0, lo1;
            split2(av0.x, av0.y, hi0.x, lo0.x); split2(av0.z, av0.w, hi0.y, lo0.y);
            split2(av1.x, av1.y, hi0.z, lo0.z); split2(av1.z, av1.w, hi0.w, lo0.w);
            split2(av2.x, av2.y, hi1.x, lo1.x); split2(av2.z, av2.w, hi1.y, lo1.y);
            split2(av3.x, av3.y, hi1.z, lo1.z); split2(av3.z, av3.w, hi1.w, lo1.w);
            *reinterpret_cast<uint4*>(ast)              = hi0;
            *reinterpret_cast<uint4*>(ast + 16)         = hi1;
            *reinterpret_cast<uint4*>(ast + 10240)      = lo0;
            *reinterpret_cast<uint4*>(ast + 10240 + 16) = lo1;
        }
        // prefetch A(g+1): stride 32 fp32 per group  (BUG FIX: was *64)
        if (g + 1 < 8) {
            const float* f = fbase + (g + 1) * 32;
            av0 = *reinterpret_cast<const float4*>(f + 0);
            av1 = *reinterpret_cast<const float4*>(f + 4);
            av2 = *reinterpret_cast<const float4*>(f + 8);
            av3 = *reinterpret_cast<const float4*>(f + 12);
        }
        __syncthreads();
        if (g + 2 < 8) ISSUE_B(g + 2);

        const uint32_t aH = sb + (uint32_t)(g & 1) * QA_STAGE + aRowOff;
        const uint32_t aL = aH + 10240;
        const uint32_t bH = sb + QSM_B + (uint32_t)(g % 3) * QB_STAGE + bRowOff;
        const uint32_t bL = bH + 10240;

#pragma unroll
        for (int ks = 0; ks < 2; ks++) {
            uint32_t ah[4][4], al[4][4], bf[2][4];
#pragma unroll
            for (int mf = 0; mf < 4; mf++)
                LDMX4(ah[mf][0], ah[mf][1], ah[mf][2], ah[mf][3],
                      aH + mf * (16 * SPITCH) + ks * 32);
#pragma unroll
            for (int n2 = 0; n2 < 2; n2++)
                LDMX4(bf[n2][0], bf[n2][1], bf[n2][2], bf[n2][3],
                      bH + n2 * (16 * SPITCH) + ks * 32);
#pragma unroll
            for (int mf = 0; mf < 4; mf++)
#pragma unroll
                for (int nf = 0; nf < 4; nf++)
                    MMA16816(acc[mf][nf], ah[mf],
                             bf[nf >> 1][(nf & 1) * 2],
                             bf[nf >> 1][(nf & 1) * 2 + 1]);
#pragma unroll
            for (int mf = 0; mf < 4; mf++)
                LDMX4(al[mf][0], al[mf][1], al[mf][2], al[mf][3],
                      aL + mf * (16 * SPITCH) + ks * 32);
#pragma unroll
            for (int mf = 0; mf < 4; mf++)
#pragma unroll
                for (int nf = 0; nf < 4; nf++)
                    MMA16816(acc[mf][nf], al[mf],
                             bf[nf >> 1][(nf & 1) * 2],
                             bf[nf >> 1][(nf & 1) * 2 + 1]);
#pragma unroll
            for (int n2 = 0; n2 < 2; n2++)
                LDMX4(bf[n2][0], bf[n2][1], bf[n2][2], bf[n2][3],
                      bL + n2 * (16 * SPITCH) + ks * 32);
#pragma unroll
            for (int mf = 0; mf < 4; mf++)
#pragma unroll
                for (int nf = 0; nf < 4; nf++)
                    MMA16816(acc[mf][nf], ah[mf],
                             bf[nf >> 1][(nf & 1) * 2],
                             bf[nf >> 1][(nf & 1) * 2 + 1]);
        }
    }
#undef ISSUE_B

    const int rbase = tileM * 128 + wm * 64 + (l >> 2);
    const int cbase = tileN * 128 + wn * 32 + (l & 3) * 2;
#pragma unroll
    for (int mf = 0; mf < 4; mf++) {
#pragma unroll
        for (int nf = 0; nf < 4; nf++) {
            const int col = cbase + nf * 8;
            const float b0 = bias[col], b1 = bias[col + 1];
            const size_t r0 = (size_t)(rbase + mf * 16) * QKVN + col;
            const size_t r1 = r0 + (size_t)8 * QKVN;
            *reinterpret_cast<uint2*>(Cout + r0) =
                make_uint2(pack_hl(acc[mf][nf][0] + b0), pack_hl(acc[mf][nf][1] + b1));
            *reinterpret_cast<uint2*>(Cout + r1) =
                make_uint2(pack_hl(acc[mf][nf][2] + b0), pack_hl(acc[mf][nf][3] + b1));
        }
    }
}

// ======================= proj GEMM (proven 128x128, 2-stage) =================
#define STAGE_BYTES (128 * SPITCH)          /* 10240 per buffer */
#define SMEM_GEMM (8 * STAGE_BYTES)         /* 81920 */

__global__ __launch_bounds__(256, 2) void gemm_proj_kernel(
    const __nv_bfloat16* __restrict__ Aext,
    const __nv_bfloat16* __restrict__ Bext,
    const float* __restrict__ bias,
    float* __restrict__ C, int Ntot) {
    extern __shared__ char gsm[];
    const uint32_t sAb = smem_u32(gsm);
    const uint32_t sBb = sAb + 4 * STAGE_BYTES;

    const int tid = threadIdx.x;
    const int w = tid >> 5, l = tid & 31;
    const int wm = w & 1, wn = w >> 1;
    const int tileN = blockIdx.x, tileM = blockIdx.y;

    const char* Ab = reinterpret_cast<const char*>(Aext) +
                     (size_t)tileM * 128 * (KSTORE * 2);
    const char* Bb = reinterpret_cast<const char*>(Bext) +
                     (size_t)tileN * 128 * (KSTORE * 2);

    const int lrow = tid >> 2;
    const int lseg = (tid & 3) * 16;

    float acc[4][4][4];
#pragma unroll
    for (int mf = 0; mf < 4; mf++)
#pragma unroll
        for (int nf = 0; nf < 4; nf++)
#pragma unroll
            for (int r = 0; r < 4; r++) acc[mf][nf][r] = 0.f;

#define ISSUE_GROUP(gg) do {                                                      \
        const int _g = (gg);                                                      \
        const uint32_t _sa = sAb + (uint32_t)(_g & 1) * (2 * STAGE_BYTES);        \
        const uint32_t _sb = sBb + (uint32_t)(_g & 1) * (2 * STAGE_BYTES);        \
        const size_t _r1 = (size_t)lrow * (KSTORE * 2);                           \
        const size_t _r2 = (size_t)(lrow + 64) * (KSTORE * 2);                    \
        const int _hc = _g * 64 + lseg;                                           \
        const int _lc = 512 + _g * 64 + lseg;                                     \
        CPASYNC16(_sa + lrow * SPITCH + lseg,              Ab + _r1 + _hc);       \
        CPASYNC16(_sa + (lrow + 64) * SPITCH + lseg,       Ab + _r2 + _hc);       \
        CPASYNC16(_sa + STAGE_BYTES + lrow * SPITCH + lseg,        Ab + _r1 + _lc); \
        CPASYNC16(_sa + STAGE_BYTES + (lrow + 64) * SPITCH + lseg, Ab + _r2 + _lc); \
        CPASYNC16(_sb + lrow * SPITCH + lseg,              Bb + _r1 + _hc);       \
        CPASYNC16(_sb + (lrow + 64) * SPITCH + lseg,       Bb + _r2 + _hc);       \
        CPASYNC16(_sb + STAGE_BYTES + lrow * SPITCH + lseg,        Bb + _r1 + _lc); \
        CPASYNC16(_sb + STAGE_BYTES + (lrow + 64) * SPITCH + lseg, Bb + _r2 + _lc); \
        CP_COMMIT();                                                              \
    } while (0)

    ISSUE_GROUP(0);
    ISSUE_GROUP(1);

    const uint32_t aRowOff = (uint32_t)(wm * 64 + (l & 15)) * SPITCH + (l >> 4) * 16;
    const uint32_t bRowOff = (uint32_t)(wn * 32 + ((l >> 4) * 8 + (l & 7))) * SPITCH +
                             ((l >> 3) & 1) * 16;

    for (int g = 0; g < 8; g++) {
        if (g < 7) CP_WAIT1(); else CP_WAIT0();
        __syncthreads();

        const uint32_t st = (uint32_t)(g & 1) * (2 * STAGE_BYTES);
        const uint32_t aH = sAb + st + aRowOff;
        const uint32_t aL = aH + STAGE_BYTES;
        const uint32_t bH = sBb + st + bRowOff;
        const uint32_t bL = bH + STAGE_BYTES;

#pragma unroll
        for (int ks = 0; ks < 2; ks++) {
            uint32_t ah[4][4], al[4][4], bf[2][4];
#pragma unroll
            for (int mf = 0; mf < 4; mf++)
                LDMX4(ah[mf][0], ah[mf][1], ah[mf][2], ah[mf][3],
                      aH + mf * (16 * SPITCH) + ks * 32);
#pragma unroll
            for (int n2 = 0; n2 < 2; n2++)
                LDMX4(bf[n2][0], bf[n2][1], bf[n2][2], bf[n2][3],
                      bH + n2 * (16 * SPITCH) + ks * 32);
#pragma unroll
            for (int mf = 0; mf < 4; mf++)
#pragma unroll
                for (int nf = 0; nf < 4; nf++)
                    MMA16816(acc[mf][nf], ah[mf],
                             bf[nf >> 1][(nf & 1) * 2],
                             bf[nf >> 1][(nf & 1) * 2 + 1]);
#pragma unroll
            for (int mf = 0; mf < 4; mf++)
                LDMX4(al[mf][0], al[mf][1], al[mf][2], al[mf][3],
                      aL + mf * (16 * SPITCH) + ks * 32);
#pragma unroll
            for (int mf = 0; mf < 4; mf++)
#pragma unroll
                for (int nf = 0; nf < 4; nf++)
                    MMA16816(acc[mf][nf], al[mf],
                             bf[nf >> 1][(nf & 1) * 2],
                             bf[nf >> 1][(nf & 1) * 2 + 1]);
#pragma unroll
            for (int n2 = 0; n2 < 2; n2++)
                LDMX4(bf[n2][0], bf[n2][1], bf[n2][2], bf[n2][3],
                      bL + n2 * (16 * SPITCH) + ks * 32);
#pragma unroll
            for (int mf = 0; mf < 4; mf++)
#pragma unroll
                for (int nf = 0; nf < 4; nf++)
                    MMA16816(acc[mf][nf], ah[mf],
                             bf[nf >> 1][(nf & 1) * 2],
                             bf[nf >> 1][(nf & 1) * 2 + 1]);
        }
        __syncthreads();
        if (g + 2 < 8) ISSUE_GROUP(g + 2);
    }
#undef ISSUE_GROUP

    const int rbase = tileM * 128 + wm * 64 + (l >> 2);
    const int cbase = tileN * 128 + wn * 32 + (l & 3) * 2;
#pragma unroll
    for (int mf = 0; mf < 4; mf++) {
#pragma unroll
        for (int nf = 0; nf < 4; nf++) {
            const int col = cbase + nf * 8;
            const float b0 = bias[col], b1 = bias[col + 1];
            const size_t r0 = (size_t)(rbase + mf * 16) * Ntot + col;
            const size_t r1 = r0 + (size_t)8 * Ntot;
            *reinterpret_cast<float2*>(C + r0) =
                make_float2(acc[mf][nf][0] + b0, acc[mf][nf][1] + b1);
            *reinterpret_cast<float2*>(C + r1) =
                make_float2(acc[mf][nf][2] + b0, acc[mf][nf][3] + b1);
        }
    }
}

// ======================= tensor-core attention v5.1 (proven) =================
#define QPITCH 144
#define KPITCH 144
#define VPITCH 144
#define OFF_Q   0
#define OFF_K   (144 * QPITCH)            /* 20736 */
#define OFF_V   (OFF_K + 144 * KPITCH)    /* 41472 */
#define SMEM_ATTN (OFF_V + 144 * VPITCH)  /* 62208 */

__global__ __launch_bounds__(288, 2) void attn_tc_kernel() {
    extern __shared__ char sm[];
    const uint32_t sb = smem_u32(sm);
    const int tid = threadIdx.x, l = tid & 31, w = tid >> 5;
    const int h = blockIdx.x, b = blockIdx.y;
    const size_t tokBase = (size_t)b * NW;

    for (int idx = tid; idx < 144 * 8; idx += 288) {
        int r = idx >> 3, d4 = (idx & 7) * 4;
        const uint32_t* src = g_qkv + (tokBase + r) * QKVN + h * HD + d4;
        char* dst = sm + r * QPITCH + d4 * 2;
#pragma unroll
        for (int mtx = 0; mtx < 3; mtx++) {
            uint4 e = *reinterpret_cast<const uint4*>(src + mtx * DIM);
            char* p = dst + mtx * (144 * QPITCH);
            *reinterpret_cast<uint2*>(p) =
                make_uint2(__byte_perm(e.x, e.y, 0x5410), __byte_perm(e.z, e.w, 0x5410));
            *reinterpret_cast<uint2*>(p + 64) =
                make_uint2(__byte_perm(e.x, e.y, 0x7632), __byte_perm(e.z, e.w, 0x7632));
        }
    }
    __syncthreads();

    float accS[18][4];
#pragma unroll
    for (int j = 0; j < 18; j++)
#pragma unroll
        for (int e = 0; e < 4; e++) accS[j][e] = 0.f;

    const uint32_t aBase = sb + OFF_Q + (w * 16 + (l & 15)) * QPITCH + (l >> 4) * 16;
    const uint32_t bBase = sb + OFF_K +
        (((l >> 4) & 1) * 8 + (l & 7)) * KPITCH + ((l >> 3) & 1) * 16;
#pragma unroll
    for (int ks = 0; ks < 2; ks++) {
        uint32_t ah[4], al[4];
        LDMX4(ah[0], ah[1], ah[2], ah[3], aBase + ks * 32);
        LDMX4(al[0], al[1], al[2], al[3], aBase + 64 + ks * 32);
#pragma unroll
        for (int jp = 0; jp < 9; jp++) {
            uint32_t bf[4];
            LDMX4(bf[0], bf[1], bf[2], bf[3],
                  bBase + jp * (16 * KPITCH) + ks * 32);
            MMA16816(accS[jp * 2],     ah, bf[0], bf[1]);
            MMA16816(accS[jp * 2 + 1], ah, bf[2], bf[3]);
            MMA16816(accS[jp * 2],     al, bf[0], bf[1]);
            MMA16816(accS[jp * 2 + 1], al, bf[2], bf[3]);
            LDMX4(bf[0], bf[1], bf[2], bf[3],
                  bBase + jp * (16 * KPITCH) + 64 + ks * 32);
            MMA16816(accS[jp * 2],     ah, bf[0], bf[1]);
            MMA16816(accS[jp * 2 + 1], ah, bf[2], bf[3]);
        }
    }

    const float* bh = g_bias + h * (NW * NW);
    const int r0 = w * 16 + (l >> 2);
    float rmax0 = -1e30f, rmax1 = -1e30f;
#pragma unroll
    for (int j = 0; j < 18; j++) {
        const int c = j * 8 + (l & 3) * 2;
        float2 b0 = *reinterpret_cast<const float2*>(bh + r0 * NW + c);
        float2 b1 = *reinterpret_cast<const float2*>(bh + (r0 + 8) * NW + c);
        accS[j][0] += b0.x; accS[j][1] += b0.y;
        accS[j][2] += b1.x; accS[j][3] += b1.y;
        rmax0 = fmaxf(rmax0, fmaxf(accS[j][0], accS[j][1]));
        rmax1 = fmaxf(rmax1, fmaxf(accS[j][2], accS[j][3]));
    }
#pragma unroll
    for (int o = 1; o <= 2; o <<= 1) {
        rmax0 = fmaxf(rmax0, __shfl_xor_sync(0xffffffff, rmax0, o));
        rmax1 = fmaxf(rmax1, __shfl_xor_sync(0xffffffff, rmax1, o));
    }

    float rsum0 = 0.f, rsum1 = 0.f;
#pragma unroll
    for (int j = 0; j < 18; j++) {
        accS[j][0] = __expf(accS[j][0] - rmax0);
        accS[j][1] = __expf(accS[j][1] - rmax0);
        accS[j][2] = __expf(accS[j][2] - rmax1);
        accS[j][3] = __expf(accS[j][3] - rmax1);
        rsum0 += accS[j][0] + accS[j][1];
        rsum1 += accS[j][2] + accS[j][3];
    }
#pragma unroll
    for (int o = 1; o <= 2; o <<= 1) {
        rsum0 += __shfl_xor_sync(0xffffffff, rsum0, o);
        rsum1 += __shfl_xor_sync(0xffffffff, rsum1, o);
    }
    const float inv0 = 1.0f / rsum0;
    const float inv1 = 1.0f / rsum1;

    float accO[4][4];
#pragma unroll
    for (int j = 0; j < 4; j++)
#pragma unroll
        for (int e = 0; e < 4; e++) accO[j][e] = 0.f;

    const uint32_t vLane = sb + OFF_V + (l & 15) * VPITCH + (l >> 4) * 16;
#pragma unroll
    for (int kk = 0; kk < 9; kk++) {
        uint32_t ph[4], pl[4];
        {
            const int j0 = 2 * kk, j1 = 2 * kk + 1;
            split2(accS[j0][0] * inv0, accS[j0][1] * inv0, ph[0], pl[0]);
            split2(accS[j0][2] * inv1, accS[j0][3] * inv1, ph[1], pl[1]);
            split2(accS[j1][0] * inv0, accS[j1][1] * inv0, ph[2], pl[2]);
            split2(accS[j1][2] * inv1, accS[j1][3] * inv1, ph[3], pl[3]);
        }
        const uint32_t vk = vLane + kk * (16 * VPITCH);
#pragma unroll
        for (int jp = 0; jp < 2; jp++) {
            uint32_t vf[4];
            LDMX4T(vf[0], vf[1], vf[2], vf[3], vk + jp * 32);
            MMA16816(accO[2 * jp],     ph, vf[0], vf[1]);
            MMA16816(accO[2 * jp + 1], ph, vf[2], vf[3]);
            MMA16816(accO[2 * jp],     pl, vf[0], vf[1]);
            MMA16816(accO[2 * jp + 1], pl, vf[2], vf[3]);
            LDMX4T(vf[0], vf[1], vf[2], vf[3], vk + jp * 32 + 64);
            MMA16816(accO[2 * jp],     ph, vf[0], vf[1]);
            MMA16816(accO[2 * jp + 1], ph, vf[2], vf[3]);
        }
    }

#pragma unroll
    for (int j = 0; j < 4; j++) {
        const int cc = j * 8 + (l & 3) * 2;
        uint32_t hp0, lp0, hp1, lp1;
        split2(accO[j][0], accO[j][1], hp0, lp0);
        split2(accO[j][2], accO[j][3], hp1, lp1);
        __nv_bfloat16* o0 = g_attx + (tokBase + r0) * KSTORE + h * HD + cc;
        __nv_bfloat16* o1 = g_attx + (tokBase + r0 + 8) * KSTORE + h * HD + cc;
        *reinterpret_cast<uint32_t*>(o0)       = hp0;
        *reinterpret_cast<uint32_t*>(o0 + 256) = lp0;
        *reinterpret_cast<uint32_t*>(o1)       = hp1;
        *reinterpret_cast<uint32_t*>(o1 + 256) = lp1;
    }
}

// ---------------- launch ------------------------------------------------------
extern "C" void kernel_launch(void* const* d_in, const int* in_sizes, int n_in,
                              void* d_out, int out_size) {
    const float* x      = (const float*)d_in[0];
    const float* qkv_w  = (const float*)d_in[1];
    const float* qkv_b  = (const float*)d_in[2];
    const float* proj_w = (const float*)d_in[3];
    const float* proj_b = (const float*)d_in[4];
    const float* rpb    = (const float*)d_in[5];
    const int*   rel    = (const int*)d_in[6];

    uint32_t* qkvbuf = nullptr;
    __nv_bfloat16 *attxp = nullptr, *bqp = nullptr, *bpp = nullptr;
    float* sbp = nullptr;
    cudaGetSymbolAddress((void**)&qkvbuf, g_qkv);
    cudaGetSymbolAddress((void**)&attxp, g_attx);
    cudaGetSymbolAddress((void**)&bqp,   g_bq);
    cudaGetSymbolAddress((void**)&bpp,   g_bp);
    cudaGetSymbolAddress((void**)&sbp,   g_sbias);

    static bool attr_done = false;
    if (!attr_done) {
        cudaFuncSetAttribute(attn_tc_kernel,
                             cudaFuncAttributeMaxDynamicSharedMemorySize, SMEM_ATTN);
        cudaFuncSetAttribute(gemm_qkv_kernel,
                             cudaFuncAttributeMaxDynamicSharedMemorySize, SMEM_QKV);
        cudaFuncSetAttribute(gemm_proj_kernel,
                             cudaFuncAttributeMaxDynamicSharedMemorySize, SMEM_GEMM);
        attr_done = true;
    }

    // order: profiled launch slot (index 3) = fused QKV GEMM
    conv_w_kernel<<<1024, 256>>>(qkv_w, proj_w);                     // 0
    build_bias_kernel<<<81, 256>>>(rpb, rel);                        // 1
    prep_bias_kernel<<<3, 256>>>(qkv_b);                             // 2
    gemm_qkv_kernel<<<dim3(QKVN / 128, NTOK / 128), 256, SMEM_QKV>>>(
        x, bqp, sbp, qkvbuf);                                        // 3 <- profiled
    attn_tc_kernel<<<dim3(NH, BnW), 288, SMEM_ATTN>>>();             // 4
    gemm_proj_kernel<<<dim3(DIM / 128, NTOK / 128), 256, SMEM_GEMM>>>(
        attxp, bpp, proj_b, (float*)d_out, DIM);                     // 5
}